// round 1
// baseline (speedup 1.0000x reference)
#include <cuda_runtime.h>
#include <math.h>

#define N 8192
#define D 512

#define BM 128
#define BN 128
#define BK 16
#define TM 8
#define TN 8

#define COL_CHUNKS 32            // row-chunks for column LSE partials
#define ROWS_PER_CHUNK (N / COL_CHUNKS)

// ---------------- device scratch (no allocations allowed in kernel_launch) ----
__device__ float g_cn[(size_t)N * D];
__device__ float g_en[(size_t)N * D];
__device__ float g_S[(size_t)N * N];       // 256 MB: cos_sim / T
__device__ float g_lse_row[N];
__device__ float g_lse_col[N];
__device__ float g_pm[COL_CHUNKS * N];     // column-LSE partial max
__device__ float g_ps[COL_CHUNKS * N];     // column-LSE partial sum

// ---------------- 1. normalize: one block per row, 128 threads, float4 -------
__global__ void knorm(const float* __restrict__ in, float* __restrict__ out) {
    int row = blockIdx.x;
    const float4* ip = reinterpret_cast<const float4*>(in + (size_t)row * D);
    float4 v = ip[threadIdx.x];                     // 128 threads * 4 = 512
    float ss = v.x * v.x + v.y * v.y + v.z * v.z + v.w * v.w;
    #pragma unroll
    for (int o = 16; o; o >>= 1) ss += __shfl_xor_sync(0xffffffffu, ss, o);
    __shared__ float sm[4];
    int w = threadIdx.x >> 5;
    if ((threadIdx.x & 31) == 0) sm[w] = ss;
    __syncthreads();
    float tot = sm[0] + sm[1] + sm[2] + sm[3];
    float inv = 1.0f / fmaxf(sqrtf(tot), 1e-8f);    // matches torch eps clamp
    float4 o4 = make_float4(v.x * inv, v.y * inv, v.z * inv, v.w * inv);
    reinterpret_cast<float4*>(out + (size_t)row * D)[threadIdx.x] = o4;
}

// ---------------- 2. SGEMM S = (cn @ en^T) / T  (128x128 tile, 8x8/thread) ---
__global__ __launch_bounds__(256, 2)
void kgemm(const float* __restrict__ tptr) {
    __shared__ float As[BK][BM];
    __shared__ float Bs[BK][BN];

    const float invT = 1.0f / *tptr;
    const int bm = blockIdx.y * BM;
    const int bn = blockIdx.x * BN;
    const int tid = threadIdx.x;
    const int tx = tid & 15;        // 16x16 thread grid
    const int ty = tid >> 4;

    float acc[TM][TN] = {};

    for (int k0 = 0; k0 < D; k0 += BK) {
        // 128 rows x 16 floats per matrix = 512 float4; 2 per thread
        #pragma unroll
        for (int l = 0; l < 2; l++) {
            int f  = tid + l * 256;          // [0, 512)
            int r  = f >> 2;                 // row within tile
            int c4 = f & 3;                  // which float4 within 16 floats
            float4 a = *reinterpret_cast<const float4*>(
                g_cn + (size_t)(bm + r) * D + k0 + c4 * 4);
            As[c4 * 4 + 0][r] = a.x; As[c4 * 4 + 1][r] = a.y;
            As[c4 * 4 + 2][r] = a.z; As[c4 * 4 + 3][r] = a.w;
            float4 b = *reinterpret_cast<const float4*>(
                g_en + (size_t)(bn + r) * D + k0 + c4 * 4);
            Bs[c4 * 4 + 0][r] = b.x; Bs[c4 * 4 + 1][r] = b.y;
            Bs[c4 * 4 + 2][r] = b.z; Bs[c4 * 4 + 3][r] = b.w;
        }
        __syncthreads();

        #pragma unroll
        for (int k = 0; k < BK; k++) {
            float af[TM], bf[TN];
            #pragma unroll
            for (int i = 0; i < TM; i++) af[i] = As[k][ty * TM + i];
            #pragma unroll
            for (int j = 0; j < TN; j++) bf[j] = Bs[k][tx * TN + j];
            #pragma unroll
            for (int i = 0; i < TM; i++)
                #pragma unroll
                for (int j = 0; j < TN; j++)
                    acc[i][j] = fmaf(af[i], bf[j], acc[i][j]);
        }
        __syncthreads();
    }

    #pragma unroll
    for (int i = 0; i < TM; i++) {
        size_t row = (size_t)(bm + ty * TM + i);
        float4* op = reinterpret_cast<float4*>(g_S + row * N + bn + tx * TN);
        float4 o0 = make_float4(acc[i][0] * invT, acc[i][1] * invT,
                                acc[i][2] * invT, acc[i][3] * invT);
        float4 o1 = make_float4(acc[i][4] * invT, acc[i][5] * invT,
                                acc[i][6] * invT, acc[i][7] * invT);
        op[0] = o0; op[1] = o1;
    }
}

// ---------------- 3. row LSE (skip diagonal == -9e15 fill), one block/row ----
__global__ void krow() {
    const int row = blockIdx.x;
    const float* __restrict__ Sr = g_S + (size_t)row * N;
    float m = -3.0e38f, s = 0.0f;
    for (int j = threadIdx.x; j < N; j += 256) {
        if (j == row) continue;                 // == exp(NEG_FILL) -> 0
        float v = Sr[j];
        if (v > m) { s = s * __expf(m - v) + 1.0f; m = v; }
        else       { s += __expf(v - m); }
    }
    __shared__ float sm[256], ssum[256];
    sm[threadIdx.x] = m; ssum[threadIdx.x] = s;
    __syncthreads();
    for (int o = 128; o; o >>= 1) {
        if (threadIdx.x < o) {
            float m1 = sm[threadIdx.x],     s1 = ssum[threadIdx.x];
            float m2 = sm[threadIdx.x + o], s2 = ssum[threadIdx.x + o];
            float mm = fmaxf(m1, m2);
            sm[threadIdx.x]   = mm;
            ssum[threadIdx.x] = s1 * __expf(m1 - mm) + s2 * __expf(m2 - mm);
        }
        __syncthreads();
    }
    if (threadIdx.x == 0) g_lse_row[row] = sm[0] + __logf(ssum[0]);
}

// ---------------- 4a. column LSE partials: coalesced row-major sweep ---------
__global__ void kcolpart() {
    const int c  = blockIdx.x * 256 + threadIdx.x;   // column owned by thread
    const int r0 = blockIdx.y * ROWS_PER_CHUNK;
    float m = -3.0e38f, s = 0.0f;
    for (int r = r0; r < r0 + ROWS_PER_CHUNK; r++) {
        if (r == c) continue;
        float v = g_S[(size_t)r * N + c];
        if (v > m) { s = s * __expf(m - v) + 1.0f; m = v; }
        else       { s += __expf(v - m); }
    }
    g_pm[blockIdx.y * N + c] = m;
    g_ps[blockIdx.y * N + c] = s;
}

// ---------------- 4b. combine column partials --------------------------------
__global__ void kcolcomb() {
    const int c = blockIdx.x * 256 + threadIdx.x;
    float m = -3.0e38f, s = 0.0f;
    #pragma unroll 4
    for (int ch = 0; ch < COL_CHUNKS; ch++) {
        float m2 = g_pm[ch * N + c], s2 = g_ps[ch * N + c];
        float mm = fmaxf(m, m2);
        s = s * __expf(m - mm) + s2 * __expf(m2 - mm);
        m = mm;
    }
    g_lse_col[c] = m + __logf(s);
}

// ---------------- 5. final: loss = mean(lse_row + lse_col - 2*diag) ----------
__global__ void kfinal(float* __restrict__ out) {
    __shared__ float red[256];
    float acc = 0.0f;
    for (int i = threadIdx.x; i < N; i += 256) {
        float d = g_S[(size_t)i * N + i];
        acc += g_lse_row[i] + g_lse_col[i] - 2.0f * d;
    }
    red[threadIdx.x] = acc;
    __syncthreads();
    for (int o = 128; o; o >>= 1) {
        if (threadIdx.x < o) red[threadIdx.x] += red[threadIdx.x + o];
        __syncthreads();
    }
    if (threadIdx.x == 0) out[0] = red[0] / (float)N;
}

// ---------------- launcher ---------------------------------------------------
extern "C" void kernel_launch(void* const* d_in, const int* in_sizes, int n_in,
                              void* d_out, int out_size) {
    const float* cxr  = (const float*)d_in[0];
    const float* ehr  = (const float*)d_in[1];
    const float* temp = (const float*)d_in[2];

    float *cn_ptr, *en_ptr;
    cudaGetSymbolAddress((void**)&cn_ptr, g_cn);
    cudaGetSymbolAddress((void**)&en_ptr, g_en);

    knorm<<<N, 128>>>(cxr, cn_ptr);
    knorm<<<N, 128>>>(ehr, en_ptr);

    dim3 gg(N / BN, N / BM);
    kgemm<<<gg, 256>>>(temp);

    krow<<<N, 256>>>();
    kcolpart<<<dim3(N / 256, COL_CHUNKS), 256>>>();
    kcolcomb<<<N / 256, 256>>>();
    kfinal<<<1, 256>>>((float*)d_out);
}

// round 3
// speedup vs baseline: 13.1538x; 13.1538x over previous
#include <cuda_runtime.h>
#include <cuda_bf16.h>
#include <cstdint>
#include <math.h>

#define NN 8192
#define DD 512

#define BM 128
#define BN 128
#define BK 64                        // bf16 cols per chunk = 128 bytes per row
#define NCHUNKS (DD / BK)            // 8
#define GRID_X (NN / BN)             // 64
#define GRID_Y (NN / BM)             // 64

// dynamic SMEM layout
#define SA 0                         // A bufs: 2 x 128*128B = 32KB
#define SB 32768                     // B bufs: 2 x 128*128B = 32KB
#define SRED 65536                   // 256 floats (row[128], col[128])
#define SMEM_TOTAL (65536 + 1024)

// ---------------- device scratch --------------------------------------------
__device__ __nv_bfloat16 g_cnb[(size_t)NN * DD];
__device__ __nv_bfloat16 g_enb[(size_t)NN * DD];
__device__ float g_prow[(size_t)GRID_X * NN];   // per n-tile row exp-sums
__device__ float g_pcol[(size_t)GRID_Y * NN];   // per m-tile col exp-sums
__device__ float g_diag[NN];
__device__ float g_lse_row[NN];
__device__ float g_lse_col[NN];

__device__ __forceinline__ uint32_t smem_u32(const void* p) {
    uint32_t a;
    asm("{ .reg .u64 t; cvta.to.shared.u64 t, %1; cvt.u32.u64 %0, t; }"
        : "=r"(a) : "l"(p));
    return a;
}

// ---------------- 1. normalize -> bf16 --------------------------------------
__global__ void knorm(const float* __restrict__ in, __nv_bfloat16* __restrict__ out) {
    int row = blockIdx.x;
    const float4* ip = reinterpret_cast<const float4*>(in + (size_t)row * DD);
    float4 v = ip[threadIdx.x];
    float ss = v.x * v.x + v.y * v.y + v.z * v.z + v.w * v.w;
    #pragma unroll
    for (int o = 16; o; o >>= 1) ss += __shfl_xor_sync(0xffffffffu, ss, o);
    __shared__ float sm[4];
    if ((threadIdx.x & 31) == 0) sm[threadIdx.x >> 5] = ss;
    __syncthreads();
    float inv = 1.0f / fmaxf(sqrtf(sm[0] + sm[1] + sm[2] + sm[3]), 1e-8f);
    __nv_bfloat162* op = reinterpret_cast<__nv_bfloat162*>(out + (size_t)row * DD);
    op[2 * threadIdx.x]     = __floats2bfloat162_rn(v.x * inv, v.y * inv);
    op[2 * threadIdx.x + 1] = __floats2bfloat162_rn(v.z * inv, v.w * inv);
}

// ---------------- 2. fused mma.sync GEMM + exp-sum epilogue -----------------
// 8 warps: warp grid 4(M) x 2(N); warp tile 32x64; frags: 2(m16) x 8(n8)
__global__ void __launch_bounds__(256, 2) kmain(const float* __restrict__ tptr) {
    extern __shared__ char smem[];
    const uint32_t smb = smem_u32(smem);
    const int tid = threadIdx.x;
    const int wid = tid >> 5, lid = tid & 31;
    const int wm = wid >> 1, wn = wid & 1;       // 4 x 2 warp grid
    const int bm = blockIdx.y * BM;
    const int bn = blockIdx.x * BN;

    float acc[2][8][4];
    #pragma unroll
    for (int i = 0; i < 2; i++)
        #pragma unroll
        for (int j = 0; j < 8; j++)
            #pragma unroll
            for (int e = 0; e < 4; e++) acc[i][j][e] = 0.0f;

    // ---- cp.async chunk loader: 128 rows x 128B, SW128-style xor swizzle ----
    auto load_chunk = [&](int chunk, int buf) {
        const char* asrc = (const char*)(g_cnb + (size_t)bm * DD + chunk * BK);
        const char* bsrc = (const char*)(g_enb + (size_t)bn * DD + chunk * BK);
        #pragma unroll
        for (int i = 0; i < 4; i++) {
            int idx = tid + i * 256;            // [0,1024)
            int r = idx >> 3, c = idx & 7;      // row, 16B-group
            uint32_t soff = r * 128 + ((c ^ (r & 7)) * 16);
            uint32_t da = smb + SA + buf * 16384 + soff;
            uint32_t db = smb + SB + buf * 16384 + soff;
            const void* ga = asrc + (size_t)r * (DD * 2) + c * 16;
            const void* gb = bsrc + (size_t)r * (DD * 2) + c * 16;
            asm volatile("cp.async.cg.shared.global [%0], [%1], 16;" :: "r"(da), "l"(ga));
            asm volatile("cp.async.cg.shared.global [%0], [%1], 16;" :: "r"(db), "l"(gb));
        }
        asm volatile("cp.async.commit_group;" ::: "memory");
    };

    // ---- compute one K-chunk (4 k16 steps) ----
    auto compute = [&](int buf) {
        const uint32_t abase = smb + SA + buf * 16384 + (wm * 32) * 128;
        const uint32_t bbase = smb + SB + buf * 16384 + (wn * 64) * 128;
        #pragma unroll
        for (int kk = 0; kk < 4; kk++) {
            const int cg = kk * 2 + (lid >> 4);       // 16B-group within row
            uint32_t a[2][4];
            #pragma unroll
            for (int mi = 0; mi < 2; mi++) {
                int r = mi * 16 + (lid & 15);
                uint32_t addr = abase + r * 128 + ((cg ^ (r & 7)) * 16);
                asm volatile("ldmatrix.sync.aligned.m8n8.x4.shared.b16 {%0,%1,%2,%3}, [%4];"
                             : "=r"(a[mi][0]), "=r"(a[mi][1]), "=r"(a[mi][2]), "=r"(a[mi][3])
                             : "r"(addr));
            }
            uint32_t b[4][4];
            #pragma unroll
            for (int nb = 0; nb < 4; nb++) {
                int r = nb * 16 + (lid & 15);
                uint32_t addr = bbase + r * 128 + ((cg ^ (r & 7)) * 16);
                asm volatile("ldmatrix.sync.aligned.m8n8.x4.shared.b16 {%0,%1,%2,%3}, [%4];"
                             : "=r"(b[nb][0]), "=r"(b[nb][1]), "=r"(b[nb][2]), "=r"(b[nb][3])
                             : "r"(addr));
            }
            #pragma unroll
            for (int mi = 0; mi < 2; mi++)
                #pragma unroll
                for (int nj = 0; nj < 8; nj++) {
                    const int nb = nj >> 1, hi = nj & 1;
                    asm volatile(
                        "mma.sync.aligned.m16n8k16.row.col.f32.bf16.bf16.f32 "
                        "{%0,%1,%2,%3}, {%4,%5,%6,%7}, {%8,%9}, {%0,%1,%2,%3};"
                        : "+f"(acc[mi][nj][0]), "+f"(acc[mi][nj][1]),
                          "+f"(acc[mi][nj][2]), "+f"(acc[mi][nj][3])
                        : "r"(a[mi][0]), "r"(a[mi][1]), "r"(a[mi][2]), "r"(a[mi][3]),
                          "r"(b[nb][hi]), "r"(b[nb][2 + hi]));
                }
        }
    };

    // ---- pipelined mainloop ----
    load_chunk(0, 0);
    #pragma unroll 1
    for (int k = 0; k < NCHUNKS; k++) {
        if (k + 1 < NCHUNKS) {
            load_chunk(k + 1, (k + 1) & 1);
            asm volatile("cp.async.wait_group 1;" ::: "memory");
        } else {
            asm volatile("cp.async.wait_group 0;" ::: "memory");
        }
        __syncthreads();
        compute(k & 1);
        __syncthreads();
    }

    // ---- epilogue: exp with fixed max M0 = 1/T, row/col partial sums ----
    float* sm_row = (float*)(smem + SRED);
    float* sm_col = sm_row + 128;
    if (tid < 128) { sm_row[tid] = 0.0f; sm_col[tid] = 0.0f; }
    __syncthreads();

    const float invT = 1.0f / *tptr;
    const float M0 = invT;
    const bool hasdiag = (bm == bn);
    float rowacc[2][2] = {};
    float colacc[8][2] = {};

    #pragma unroll
    for (int mi = 0; mi < 2; mi++)
        #pragma unroll
        for (int nj = 0; nj < 8; nj++)
            #pragma unroll
            for (int e = 0; e < 4; e++) {
                const int h = e >> 1, p = e & 1;
                float logit = acc[mi][nj][e] * invT;
                float ex = __expf(logit - M0);
                if (hasdiag) {
                    int gr = wm * 32 + mi * 16 + h * 8 + (lid >> 2);
                    int gc = wn * 64 + nj * 8 + (lid & 3) * 2 + p;
                    if (gr == gc) { g_diag[bm + gr] = logit; ex = 0.0f; }
                }
                rowacc[mi][h] += ex;
                colacc[nj][p] += ex;
            }

    #pragma unroll
    for (int mi = 0; mi < 2; mi++)
        #pragma unroll
        for (int h = 0; h < 2; h++) {
            float v = rowacc[mi][h];
            v += __shfl_xor_sync(0xffffffffu, v, 1);
            v += __shfl_xor_sync(0xffffffffu, v, 2);
            if ((lid & 3) == 0)
                atomicAdd(&sm_row[wm * 32 + mi * 16 + h * 8 + (lid >> 2)], v);
        }
    #pragma unroll
    for (int nj = 0; nj < 8; nj++)
        #pragma unroll
        for (int p = 0; p < 2; p++) {
            float v = colacc[nj][p];
            v += __shfl_xor_sync(0xffffffffu, v, 4);
            v += __shfl_xor_sync(0xffffffffu, v, 8);
            v += __shfl_xor_sync(0xffffffffu, v, 16);
            if (lid < 4)
                atomicAdd(&sm_col[wn * 64 + nj * 8 + (lid & 3) * 2 + p], v);
        }
    __syncthreads();

    if (tid < 128) {
        g_prow[(size_t)blockIdx.x * NN + bm + tid] = sm_row[tid];
        g_pcol[(size_t)blockIdx.y * NN + bn + tid] = sm_col[tid];
    }
}

// ---------------- 3. reduce partials -> LSE ---------------------------------
__global__ void krowlse(const float* __restrict__ tptr) {
    int r = blockIdx.x * 256 + threadIdx.x;
    float M0 = 1.0f / *tptr;
    float s = 0.0f;
    #pragma unroll 8
    for (int t = 0; t < GRID_X; t++) s += g_prow[(size_t)t * NN + r];
    g_lse_row[r] = M0 + __logf(s);
}
__global__ void kcollse(const float* __restrict__ tptr) {
    int c = blockIdx.x * 256 + threadIdx.x;
    float M0 = 1.0f / *tptr;
    float s = 0.0f;
    #pragma unroll 8
    for (int t = 0; t < GRID_Y; t++) s += g_pcol[(size_t)t * NN + c];
    g_lse_col[c] = M0 + __logf(s);
}

// ---------------- 4. final scalar -------------------------------------------
__global__ void kfinal(float* __restrict__ out) {
    __shared__ float red[256];
    float acc = 0.0f;
    for (int i = threadIdx.x; i < NN; i += 256)
        acc += g_lse_row[i] + g_lse_col[i] - 2.0f * g_diag[i];
    red[threadIdx.x] = acc;
    __syncthreads();
    for (int o = 128; o; o >>= 1) {
        if (threadIdx.x < o) red[threadIdx.x] += red[threadIdx.x + o];
        __syncthreads();
    }
    if (threadIdx.x == 0) out[0] = red[0] / (float)NN;
}

// ---------------- launcher ---------------------------------------------------
extern "C" void kernel_launch(void* const* d_in, const int* in_sizes, int n_in,
                              void* d_out, int out_size) {
    const float* cxr  = (const float*)d_in[0];
    const float* ehr  = (const float*)d_in[1];
    const float* temp = (const float*)d_in[2];

    __nv_bfloat16 *cnb, *enb;
    cudaGetSymbolAddress((void**)&cnb, g_cnb);
    cudaGetSymbolAddress((void**)&enb, g_enb);

    cudaFuncSetAttribute(kmain, cudaFuncAttributeMaxDynamicSharedMemorySize,
                         SMEM_TOTAL);

    knorm<<<NN, 128>>>(cxr, cnb);
    knorm<<<NN, 128>>>(ehr, enb);
    kmain<<<dim3(GRID_X, GRID_Y), 256, SMEM_TOTAL>>>(temp);
    krowlse<<<NN / 256, 256>>>(temp);
    kcollse<<<NN / 256, 256>>>(temp);
    kfinal<<<1, 256>>>((float*)d_out);
}